// round 3
// baseline (speedup 1.0000x reference)
#include <cuda_runtime.h>
#include <math.h>

// Problem constants (from reference)
#define NN   50000
#define EE   1600000
#define HDIM 128

// ---------------- static device scratch (allocation-free) ----------------
__device__ __align__(16) int   g_src[EE];
__device__ __align__(16) int   g_dst[EE];
__device__ __align__(16) float g_deg[NN];
__device__ __align__(16) float g_dis[NN];
__device__ __align__(16) float g_h  [(size_t)NN * HDIM];
__device__ __align__(16) float g_hg [(size_t)NN * HDIM];
__device__ __align__(16) float g_hs [(size_t)NN * HDIM];
__device__ __align__(16) float g_agg[(size_t)NN * HDIM];

// ---------------- math helpers ----------------
__device__ __forceinline__ float mishf(float x) {
    // softplus via logaddexp(x, 0) = max(x,0) + log1p(exp(-|x|))  (matches jax.nn.softplus)
    float sp = fmaxf(x, 0.0f) + log1pf(expf(-fabsf(x)));
    return x * tanhf(sp);
}

// ---------------- small kernels ----------------
__global__ void init_deg_kernel(int n) {
    int i = blockIdx.x * blockDim.x + threadIdx.x;
    if (i < n) g_deg[i] = 1.0f;   // self-loop contributes 1 to every node's degree
}

// edge_index arrives as int32 (JAX default x64-disabled downcasts int64 -> int32).
__global__ void build_edges_kernel(const int* __restrict__ ei, int e, int n) {
    int i = blockIdx.x * blockDim.x + threadIdx.x;
    if (i < e) {
        int s = ei[i];
        int d = ei[e + i];
        // defensive clamp: never trap on unexpected index encoding
        if ((unsigned)s >= (unsigned)n) s = 0;
        if ((unsigned)d >= (unsigned)n) d = 0;
        g_src[i] = s;
        g_dst[i] = d;
        atomicAdd(&g_deg[d], 1.0f);
    }
}

__global__ void dis_kernel(int n) {
    int i = blockIdx.x * blockDim.x + threadIdx.x;
    if (i < n) g_dis[i] = rsqrtf(g_deg[i]);
}

__global__ void zero_agg_kernel(int n4) {
    int i = blockIdx.x * blockDim.x + threadIdx.x;
    if (i < n4) reinterpret_cast<float4*>(g_agg)[i] = make_float4(0.f, 0.f, 0.f, 0.f);
}

// ---------------- SGEMM: M x 128 x 128, row-major A and B ----------------
// MODE 0: A = external x,  C = g_h,  C = mish(acc + bias)   (preprocess)
// MODE 1: A = g_h,         C = g_hg, C = acc                (gcn branch, raw)
// MODE 2: A = g_h,         C = g_hs, C = acc + bias         (skip branch)
template <int MODE>
__global__ __launch_bounds__(256) void sgemm128_kernel(
    const float* __restrict__ Aext,
    const float* __restrict__ B,
    const float* __restrict__ bias,
    int M)
{
    const int K = 128, Ncols = 128;
    __shared__ float As[16][128];   // transposed: As[k][m]
    __shared__ float Bs[16][128];   // Bs[k][n]

    const float* __restrict__ A = (MODE == 0) ? Aext : g_h;
    float* __restrict__ C = (MODE == 0) ? g_h : (MODE == 1 ? g_hg : g_hs);

    int tid = threadIdx.x;
    int block_row = blockIdx.x * 128;
    int tx = tid & 15;   // col group (8 cols each)
    int ty = tid >> 4;   // row group (8 rows each)

    float acc[8][8];
#pragma unroll
    for (int i = 0; i < 8; i++)
#pragma unroll
        for (int j = 0; j < 8; j++) acc[i][j] = 0.0f;

    for (int k0 = 0; k0 < K; k0 += 16) {
        // Load A tile (128 rows x 16 cols) as float4, store transposed
#pragma unroll
        for (int it = 0; it < 2; it++) {
            int f4 = tid + it * 256;           // 0..511
            int r  = f4 >> 2;                  // 0..127
            int c  = (f4 & 3) * 4;             // 0,4,8,12
            int gr = block_row + r;
            float4 a = make_float4(0.f, 0.f, 0.f, 0.f);
            if (gr < M)
                a = *reinterpret_cast<const float4*>(A + (size_t)gr * K + k0 + c);
            As[c + 0][r] = a.x;
            As[c + 1][r] = a.y;
            As[c + 2][r] = a.z;
            As[c + 3][r] = a.w;
        }
        // Load B tile (16 rows x 128 cols) as float4
#pragma unroll
        for (int it = 0; it < 2; it++) {
            int f4 = tid + it * 256;           // 0..511
            int r  = f4 >> 5;                  // 0..15
            int c  = (f4 & 31) * 4;            // 0..124
            float4 b = *reinterpret_cast<const float4*>(B + (size_t)(k0 + r) * Ncols + c);
            *reinterpret_cast<float4*>(&Bs[r][c]) = b;
        }
        __syncthreads();

#pragma unroll
        for (int kk = 0; kk < 16; kk++) {
            float ra[8], rb[8];
            *reinterpret_cast<float4*>(ra)     = *reinterpret_cast<const float4*>(&As[kk][ty * 8]);
            *reinterpret_cast<float4*>(ra + 4) = *reinterpret_cast<const float4*>(&As[kk][ty * 8 + 4]);
            *reinterpret_cast<float4*>(rb)     = *reinterpret_cast<const float4*>(&Bs[kk][tx * 8]);
            *reinterpret_cast<float4*>(rb + 4) = *reinterpret_cast<const float4*>(&Bs[kk][tx * 8 + 4]);
#pragma unroll
            for (int i = 0; i < 8; i++)
#pragma unroll
                for (int j = 0; j < 8; j++)
                    acc[i][j] = fmaf(ra[i], rb[j], acc[i][j]);
        }
        __syncthreads();
    }

    // Epilogue
#pragma unroll
    for (int i = 0; i < 8; i++) {
        int gr = block_row + ty * 8 + i;
        if (gr >= M) continue;
        float* crow = C + (size_t)gr * Ncols + tx * 8;
#pragma unroll
        for (int j = 0; j < 8; j++) {
            float v = acc[i][j];
            if (MODE == 0) { v += bias[tx * 8 + j]; v = mishf(v); }
            else if (MODE == 2) { v += bias[tx * 8 + j]; }
            crow[j] = v;
        }
    }
}

// ---------------- edge aggregation: agg[dst] += dis[src]*dis[dst]*hg[src] ----------------
// One warp handles 4 edges; each lane owns a float4 (128 floats / 32 lanes).
// atomicAdd with unused return compiles to RED.E.ADD.F32 (no result round-trip).
__global__ __launch_bounds__(256) void edge_agg_kernel(int e) {
    int gw   = (blockIdx.x * blockDim.x + threadIdx.x) >> 5;
    int lane = threadIdx.x & 31;
    int e0 = gw * 4;
    if (e0 >= e) return;

    int   s[4], d[4];
    float n[4];
    float4 v[4];
    bool ok[4];
#pragma unroll
    for (int i = 0; i < 4; i++) {
        int ed = e0 + i;
        ok[i] = ed < e;
        if (ok[i]) {
            s[i] = g_src[ed];
            d[i] = g_dst[ed];
            n[i] = g_dis[s[i]] * g_dis[d[i]];
            v[i] = *reinterpret_cast<const float4*>(g_hg + (size_t)s[i] * HDIM + lane * 4);
        }
    }
#pragma unroll
    for (int i = 0; i < 4; i++) {
        if (ok[i]) {
            float* a = g_agg + (size_t)d[i] * HDIM + lane * 4;
            atomicAdd(a + 0, v[i].x * n[i]);
            atomicAdd(a + 1, v[i].y * n[i]);
            atomicAdd(a + 2, v[i].z * n[i]);
            atomicAdd(a + 3, v[i].w * n[i]);
        }
    }
}

// ---------------- layer epilogue: h = mish(agg + dis^2*hg + gcn_b + hs) ----------------
// dis^2*hg is the self-loop message (src == dst), fused here instead of materializing
// self-loop edges.
__global__ void layer_epilogue_kernel(const float* __restrict__ gcn_b_l, int n4) {
    int i = blockIdx.x * blockDim.x + threadIdx.x;
    if (i >= n4) return;
    int row = i >> 5;      // 32 float4 per row
    int c4  = i & 31;
    float sl = g_dis[row]; sl *= sl;
    float4 a = reinterpret_cast<const float4*>(g_agg)[i];
    float4 g = reinterpret_cast<const float4*>(g_hg)[i];
    float4 s = reinterpret_cast<const float4*>(g_hs)[i];
    float4 b = reinterpret_cast<const float4*>(gcn_b_l)[c4];
    float4 o;
    o.x = mishf(a.x + b.x + s.x + sl * g.x);
    o.y = mishf(a.y + b.y + s.y + sl * g.y);
    o.z = mishf(a.z + b.z + s.z + sl * g.z);
    o.w = mishf(a.w + b.w + s.w + sl * g.w);
    reinterpret_cast<float4*>(g_h)[i] = o;
}

// ---------------- post: out[i] = dot(h[i,:], W_post) + b_post ----------------
__global__ void post_kernel(const float* __restrict__ Wp,
                            const float* __restrict__ bp,
                            float* __restrict__ out, int M) {
    int warp = (blockIdx.x * blockDim.x + threadIdx.x) >> 5;
    int lane = threadIdx.x & 31;
    if (warp >= M) return;
    float4 hv = *reinterpret_cast<const float4*>(g_h + (size_t)warp * HDIM + lane * 4);
    float4 wv = *reinterpret_cast<const float4*>(Wp + lane * 4);
    float sum = hv.x * wv.x + hv.y * wv.y + hv.z * wv.z + hv.w * wv.w;
#pragma unroll
    for (int o = 16; o > 0; o >>= 1) sum += __shfl_xor_sync(0xFFFFFFFFu, sum, o);
    if (lane == 0) out[warp] = sum + bp[0];
}

// ---------------- launch ----------------
extern "C" void kernel_launch(void* const* d_in, const int* in_sizes, int n_in,
                              void* d_out, int out_size) {
    const float* x      = (const float*)d_in[0];
    const int*   ei     = (const int*)d_in[1];     // int32! (JAX x64-disabled)
    const float* W_pre  = (const float*)d_in[2];
    const float* b_pre  = (const float*)d_in[3];
    const float* gcn_W  = (const float*)d_in[4];
    const float* gcn_b  = (const float*)d_in[5];
    const float* skip_W = (const float*)d_in[6];
    const float* skip_b = (const float*)d_in[7];
    const float* W_post = (const float*)d_in[8];
    const float* b_post = (const float*)d_in[9];
    float*       out    = (float*)d_out;

    const int M = in_sizes[0] / HDIM;          // 50000
    const int E = in_sizes[1] / 2;             // 1600000
    const int L = in_sizes[4] / (HDIM * HDIM); // 3
    const int n4 = M * (HDIM / 4);             // float4 count of an [M,H] buffer

    const int TB = 256;
    const int gemm_blocks = (M + 127) / 128;
    const int node_blocks = (M + TB - 1) / TB;
    const int edge_blocks = (E + TB - 1) / TB;
    const int n4_blocks   = (n4 + TB - 1) / TB;
    const int agg_warps   = (E + 3) / 4;
    const int agg_blocks  = (agg_warps * 32 + TB - 1) / TB;
    const int post_blocks = (M * 32 + TB - 1) / TB;

    // Degrees + normalization
    init_deg_kernel<<<node_blocks, TB>>>(M);
    build_edges_kernel<<<edge_blocks, TB>>>(ei, E, M);
    dis_kernel<<<node_blocks, TB>>>(M);

    // Preprocess: h = mish(x @ W_pre + b_pre)
    sgemm128_kernel<0><<<gemm_blocks, TB>>>(x, W_pre, b_pre, M);

    // GCN layers
    for (int l = 0; l < L; l++) {
        const float* gW = gcn_W  + (size_t)l * HDIM * HDIM;
        const float* sW = skip_W + (size_t)l * HDIM * HDIM;
        const float* gb = gcn_b  + (size_t)l * HDIM;
        const float* sb = skip_b + (size_t)l * HDIM;

        sgemm128_kernel<1><<<gemm_blocks, TB>>>(nullptr, gW, nullptr, M); // hg = h @ gcn_W
        sgemm128_kernel<2><<<gemm_blocks, TB>>>(nullptr, sW, sb,      M); // hs = h @ skip_W + skip_b
        zero_agg_kernel<<<n4_blocks, TB>>>(n4);
        edge_agg_kernel<<<agg_blocks, TB>>>(E);
        layer_epilogue_kernel<<<n4_blocks, TB>>>(gb, n4);
    }

    // Postprocess
    post_kernel<<<post_blocks, TB>>>(W_post, b_post, out, M);
}

// round 4
// speedup vs baseline: 1.8990x; 1.8990x over previous
#include <cuda_runtime.h>
#include <math.h>

// Problem constants (from reference)
#define NN   50000
#define EE   1600000
#define HDIM 128

// ---------------- static device scratch (allocation-free) ----------------
__device__ __align__(16) int   g_src[EE];
__device__ __align__(16) int   g_dst[EE];
__device__ __align__(16) float g_deg[NN];
__device__ __align__(16) float g_dis[NN];
__device__ __align__(16) float g_h  [(size_t)NN * HDIM];
__device__ __align__(16) float g_hg [(size_t)NN * HDIM];
__device__ __align__(16) float g_agg[(size_t)NN * HDIM];

// ---------------- math helpers ----------------
__device__ __forceinline__ float mishf(float x) {
    float sp = fmaxf(x, 0.0f) + log1pf(expf(-fabsf(x)));
    return x * tanhf(sp);
}

// ---------------- small kernels ----------------
__global__ void init_deg_kernel(int n) {
    int i = blockIdx.x * blockDim.x + threadIdx.x;
    if (i < n) g_deg[i] = 1.0f;   // self-loop contributes 1
}

// edge_index arrives as int32 (JAX default x64-disabled)
__global__ void build_edges_kernel(const int* __restrict__ ei, int e, int n) {
    int i = blockIdx.x * blockDim.x + threadIdx.x;
    if (i < e) {
        int s = ei[i];
        int d = ei[e + i];
        if ((unsigned)s >= (unsigned)n) s = 0;
        if ((unsigned)d >= (unsigned)n) d = 0;
        g_src[i] = s;
        g_dst[i] = d;
        atomicAdd(&g_deg[d], 1.0f);
    }
}

__global__ void dis_kernel(int n) {
    int i = blockIdx.x * blockDim.x + threadIdx.x;
    if (i < n) g_dis[i] = rsqrtf(g_deg[i]);
}

// ---------------- SGEMM: M x 128 x 128, row-major A and B ----------------
// MODE 0: A = x,   C = g_h,   C = mish(acc + bias)          (preprocess)
// MODE 1: A = g_h, C = g_hg,  C = acc                       (gcn branch)
// MODE 3: A = g_h, C = g_agg, C = acc + skip_b + gcn_b + dis^2*hg  (skip + agg init)
template <int MODE>
__global__ __launch_bounds__(256) void sgemm128_kernel(
    const float* __restrict__ Aext,
    const float* __restrict__ B,
    const float* __restrict__ bias,
    const float* __restrict__ bias2,
    int M)
{
    const int K = 128, Ncols = 128;
    __shared__ float As[16][128];
    __shared__ float Bs[16][128];

    const float* __restrict__ A = (MODE == 0) ? Aext : g_h;
    float* __restrict__ C = (MODE == 0) ? g_h : (MODE == 1 ? g_hg : g_agg);

    int tid = threadIdx.x;
    int block_row = blockIdx.x * 128;
    int tx = tid & 15;
    int ty = tid >> 4;

    float acc[8][8];
#pragma unroll
    for (int i = 0; i < 8; i++)
#pragma unroll
        for (int j = 0; j < 8; j++) acc[i][j] = 0.0f;

    for (int k0 = 0; k0 < K; k0 += 16) {
#pragma unroll
        for (int it = 0; it < 2; it++) {
            int f4 = tid + it * 256;
            int r  = f4 >> 2;
            int c  = (f4 & 3) * 4;
            int gr = block_row + r;
            float4 a = make_float4(0.f, 0.f, 0.f, 0.f);
            if (gr < M)
                a = *reinterpret_cast<const float4*>(A + (size_t)gr * K + k0 + c);
            As[c + 0][r] = a.x;
            As[c + 1][r] = a.y;
            As[c + 2][r] = a.z;
            As[c + 3][r] = a.w;
        }
#pragma unroll
        for (int it = 0; it < 2; it++) {
            int f4 = tid + it * 256;
            int r  = f4 >> 5;
            int c  = (f4 & 31) * 4;
            float4 b = *reinterpret_cast<const float4*>(B + (size_t)(k0 + r) * Ncols + c);
            *reinterpret_cast<float4*>(&Bs[r][c]) = b;
        }
        __syncthreads();

#pragma unroll
        for (int kk = 0; kk < 16; kk++) {
            float ra[8], rb[8];
            *reinterpret_cast<float4*>(ra)     = *reinterpret_cast<const float4*>(&As[kk][ty * 8]);
            *reinterpret_cast<float4*>(ra + 4) = *reinterpret_cast<const float4*>(&As[kk][ty * 8 + 4]);
            *reinterpret_cast<float4*>(rb)     = *reinterpret_cast<const float4*>(&Bs[kk][tx * 8]);
            *reinterpret_cast<float4*>(rb + 4) = *reinterpret_cast<const float4*>(&Bs[kk][tx * 8 + 4]);
#pragma unroll
            for (int i = 0; i < 8; i++)
#pragma unroll
                for (int j = 0; j < 8; j++)
                    acc[i][j] = fmaf(ra[i], rb[j], acc[i][j]);
        }
        __syncthreads();
    }

#pragma unroll
    for (int i = 0; i < 8; i++) {
        int gr = block_row + ty * 8 + i;
        if (gr >= M) continue;
        float* crow = C + (size_t)gr * Ncols + tx * 8;
        float sl = 0.0f;
        float hgv[8];
        if (MODE == 3) {
            sl = g_dis[gr]; sl *= sl;
            const float* hr = g_hg + (size_t)gr * Ncols + tx * 8;
            *reinterpret_cast<float4*>(hgv)     = *reinterpret_cast<const float4*>(hr);
            *reinterpret_cast<float4*>(hgv + 4) = *reinterpret_cast<const float4*>(hr + 4);
        }
#pragma unroll
        for (int j = 0; j < 8; j++) {
            float v = acc[i][j];
            if (MODE == 0) { v += bias[tx * 8 + j]; v = mishf(v); }
            else if (MODE == 3) {
                v += bias[tx * 8 + j] + bias2[tx * 8 + j] + sl * hgv[j];
            }
            crow[j] = v;
        }
    }
}

// ---------------- edge aggregation: agg[dst] += dis[src]*dis[dst]*hg[src] ----------------
// 8 edges per warp; each lane owns one float4 of the 128-float row.
// red.global.add.v4.f32 with an explicit cvta-to-global address (4x fewer LTS ops
// than scalar RED).
#define EPW 8
__global__ __launch_bounds__(256) void edge_agg_kernel(int e) {
    int gw   = (blockIdx.x * blockDim.x + threadIdx.x) >> 5;
    int lane = threadIdx.x & 31;
    int e0 = gw * EPW;
    if (e0 >= e) return;

    int   s[EPW], d[EPW];
    float n[EPW];
    float4 v[EPW];
    bool ok[EPW];
#pragma unroll
    for (int i = 0; i < EPW; i++) {
        int ed = e0 + i;
        ok[i] = ed < e;
        if (ok[i]) {
            s[i] = g_src[ed];
            d[i] = g_dst[ed];
            n[i] = g_dis[s[i]] * g_dis[d[i]];
            v[i] = *reinterpret_cast<const float4*>(g_hg + (size_t)s[i] * HDIM + lane * 4);
        }
    }
#pragma unroll
    for (int i = 0; i < EPW; i++) {
        if (ok[i]) {
            size_t ga = __cvta_generic_to_global(g_agg + (size_t)d[i] * HDIM + lane * 4);
            asm volatile("red.global.add.v4.f32 [%0], {%1, %2, %3, %4};"
                         :: "l"(ga),
                            "f"(v[i].x * n[i]), "f"(v[i].y * n[i]),
                            "f"(v[i].z * n[i]), "f"(v[i].w * n[i])
                         : "memory");
        }
    }
}

// ---------------- layer epilogue: h = mish(agg) ----------------
__global__ void mish_kernel(int n4) {
    int i = blockIdx.x * blockDim.x + threadIdx.x;
    if (i >= n4) return;
    float4 a = reinterpret_cast<const float4*>(g_agg)[i];
    float4 o;
    o.x = mishf(a.x);
    o.y = mishf(a.y);
    o.z = mishf(a.z);
    o.w = mishf(a.w);
    reinterpret_cast<float4*>(g_h)[i] = o;
}

// ---------------- post: out[i] = dot(h[i,:], W_post) + b_post ----------------
__global__ void post_kernel(const float* __restrict__ Wp,
                            const float* __restrict__ bp,
                            float* __restrict__ out, int M) {
    int warp = (blockIdx.x * blockDim.x + threadIdx.x) >> 5;
    int lane = threadIdx.x & 31;
    if (warp >= M) return;
    float4 hv = *reinterpret_cast<const float4*>(g_h + (size_t)warp * HDIM + lane * 4);
    float4 wv = *reinterpret_cast<const float4*>(Wp + lane * 4);
    float sum = hv.x * wv.x + hv.y * wv.y + hv.z * wv.z + hv.w * wv.w;
#pragma unroll
    for (int o = 16; o > 0; o >>= 1) sum += __shfl_xor_sync(0xFFFFFFFFu, sum, o);
    if (lane == 0) out[warp] = sum + bp[0];
}

// ---------------- launch ----------------
extern "C" void kernel_launch(void* const* d_in, const int* in_sizes, int n_in,
                              void* d_out, int out_size) {
    const float* x      = (const float*)d_in[0];
    const int*   ei     = (const int*)d_in[1];     // int32 (JAX x64-disabled)
    const float* W_pre  = (const float*)d_in[2];
    const float* b_pre  = (const float*)d_in[3];
    const float* gcn_W  = (const float*)d_in[4];
    const float* gcn_b  = (const float*)d_in[5];
    const float* skip_W = (const float*)d_in[6];
    const float* skip_b = (const float*)d_in[7];
    const float* W_post = (const float*)d_in[8];
    const float* b_post = (const float*)d_in[9];
    float*       out    = (float*)d_out;

    const int M = in_sizes[0] / HDIM;          // 50000
    const int E = in_sizes[1] / 2;             // 1600000
    const int L = in_sizes[4] / (HDIM * HDIM); // 3
    const int n4 = M * (HDIM / 4);

    const int TB = 256;
    const int gemm_blocks = (M + 127) / 128;
    const int node_blocks = (M + TB - 1) / TB;
    const int edge_blocks = (E + TB - 1) / TB;
    const int n4_blocks   = (n4 + TB - 1) / TB;
    const int agg_warps   = (E + EPW - 1) / EPW;
    const int agg_blocks  = (agg_warps * 32 + TB - 1) / TB;
    const int post_blocks = (M * 32 + TB - 1) / TB;

    // Degrees + normalization
    init_deg_kernel<<<node_blocks, TB>>>(M);
    build_edges_kernel<<<edge_blocks, TB>>>(ei, E, M);
    dis_kernel<<<node_blocks, TB>>>(M);

    // Preprocess: h = mish(x @ W_pre + b_pre)
    sgemm128_kernel<0><<<gemm_blocks, TB>>>(x, W_pre, b_pre, nullptr, M);

    // GCN layers
    for (int l = 0; l < L; l++) {
        const float* gW = gcn_W  + (size_t)l * HDIM * HDIM;
        const float* sW = skip_W + (size_t)l * HDIM * HDIM;
        const float* gb = gcn_b  + (size_t)l * HDIM;
        const float* sb = skip_b + (size_t)l * HDIM;

        // hg = h @ gcn_W
        sgemm128_kernel<1><<<gemm_blocks, TB>>>(nullptr, gW, nullptr, nullptr, M);
        // agg = h @ skip_W + skip_b + gcn_b + dis^2*hg   (skip branch + self-loop + biases)
        sgemm128_kernel<3><<<gemm_blocks, TB>>>(nullptr, sW, sb, gb, M);
        // agg += sum_{edges} dis[s]*dis[d]*hg[s]
        edge_agg_kernel<<<agg_blocks, TB>>>(E);
        // h = mish(agg)
        mish_kernel<<<n4_blocks, TB>>>(n4);
    }

    // Postprocess
    post_kernel<<<post_blocks, TB>>>(W_post, b_post, out, M);
}